// round 1
// baseline (speedup 1.0000x reference)
#include <cuda_runtime.h>

// Problem constants (fixed dataset: B=16384, S=8, D=128, P=65536)
#define SB 8            // samples per item
#define DD 128          // embedding dim
#define ROW_F4 (DD / 4) // 32 float4 per row
#define PAIRS_PER_BLOCK 8
#define MAX_ROWS (16384 * SB)
#define MAX_BLOCKS 8192
#define EPSV 1e-6f

__device__ float g_norms[MAX_ROWS];
__device__ float g_block_sums[MAX_BLOCKS];

// ---------------------------------------------------------------------------
// Kernel 1: per-row squared norms. One warp per row (128 floats = 32 x float4).
// ---------------------------------------------------------------------------
__global__ void __launch_bounds__(256) norm_kernel(const float* __restrict__ z, int rows) {
    int warp = (blockIdx.x * 256 + threadIdx.x) >> 5;
    int lane = threadIdx.x & 31;
    if (warp >= rows) return;
    float4 v = reinterpret_cast<const float4*>(z)[warp * ROW_F4 + lane];
    float s = fmaf(v.x, v.x, fmaf(v.y, v.y, fmaf(v.z, v.z, v.w * v.w)));
#pragma unroll
    for (int m = 16; m; m >>= 1) s += __shfl_xor_sync(0xffffffffu, s, m);
    if (lane == 0) g_norms[warp] = s;
}

// ---------------------------------------------------------------------------
// Multi-value butterfly reduction stage: halves the live value count, pairing
// lane with lane^M. After stages 16,8,4,2,1 on 32 values, lane l holds the
// fully-reduced value with original index v == l in acc[0].
// ---------------------------------------------------------------------------
template <int M>
__device__ __forceinline__ void bfly(float* acc, int lane) {
    bool hi = (lane & M) != 0;
#pragma unroll
    for (int t = 0; t < M; t++) {
        float send = hi ? acc[t] : acc[t + M];
        float recv = __shfl_xor_sync(0xffffffffu, send, M);
        acc[t] = (hi ? acc[t + M] : acc[t]) + recv;
    }
}

// ---------------------------------------------------------------------------
// Kernel 2: main HIB criterion. One warp per pair index.
//   lane owns k-chunk [4*lane, 4*lane+4) of D=128.
//   Per matrix: load 16 rows (16 x LDG.128), 2 half-Gram (8x4) accumulations,
//   butterfly-reduce, pointwise sigmoid/log, accumulate.
// ---------------------------------------------------------------------------
__global__ void __launch_bounds__(256) hib_kernel(
    const float* __restrict__ z,
    const float* __restrict__ alpha_p,
    const float* __restrict__ beta_p,
    const int* __restrict__ ap, const int* __restrict__ pp,
    const int* __restrict__ an, const int* __restrict__ nn,
    int P)
{
    int lane = threadIdx.x & 31;
    int wib  = threadIdx.x >> 5;
    int pair = blockIdx.x * PAIRS_PER_BLOCK + wib;

    float beta = __ldg(beta_p);
    float a = log1pf(__expf(__ldg(alpha_p)));  // softplus(alpha)

    float total = 0.0f;

    if (pair < P) {
        int iA[2], iB[2];
        iA[0] = __ldg(ap + pair); iB[0] = __ldg(pp + pair);
        iA[1] = __ldg(an + pair); iB[1] = __ldg(nn + pair);

#pragma unroll
        for (int m = 0; m < 2; m++) {
            const float4* Za = reinterpret_cast<const float4*>(z) + (size_t)iA[m] * (SB * ROW_F4);
            const float4* Zb = reinterpret_cast<const float4*>(z) + (size_t)iB[m] * (SB * ROW_F4);
            float4 av[SB], bv[SB];
#pragma unroll
            for (int i = 0; i < SB; i++) av[i] = Za[i * ROW_F4 + lane];
#pragma unroll
            for (int j = 0; j < SB; j++) bv[j] = Zb[j * ROW_F4 + lane];

            // row index this lane will own after the butterfly: i = lane>>2
            float na = g_norms[iA[m] * SB + (lane >> 2)];

#pragma unroll
            for (int h = 0; h < 2; h++) {           // j in [4h, 4h+4)
                float acc[32];
#pragma unroll
                for (int i = 0; i < SB; i++) {
#pragma unroll
                    for (int jj = 0; jj < 4; jj++) {
                        float4 x = av[i];
                        float4 y = bv[h * 4 + jj];
                        acc[i * 4 + jj] =
                            fmaf(x.x, y.x, fmaf(x.y, y.y, fmaf(x.z, y.z, x.w * y.w)));
                    }
                }
                bfly<16>(acc, lane);
                bfly<8>(acc, lane);
                bfly<4>(acc, lane);
                bfly<2>(acc, lane);
                bfly<1>(acc, lane);
                // lane now holds dot(i=lane>>2, j=4h+(lane&3)) in acc[0]
                float nb = g_norms[iB[m] * SB + h * 4 + (lane & 3)];
                float d2 = na + nb - 2.0f * acc[0];
                float y0 = fmaf(-a, d2, beta);       // -a*d2 + beta
                float term;
                if (m == 0) {
                    // -log(sigmoid(y0) + EPS)
                    float sg = __fdividef(1.0f, 1.0f + __expf(-y0));
                    term = -__logf(sg + EPSV);
                } else {
                    // -log(1 - sigmoid(y0) - EPS) = -log(sigmoid(-y0) - EPS)
                    float sg = __fdividef(1.0f, 1.0f + __expf(y0));
                    term = -__logf(sg - EPSV);
                }
                total += term;
            }
        }
    }

    // warp reduce the 4 per-lane terms summed above
#pragma unroll
    for (int m = 16; m; m >>= 1) total += __shfl_xor_sync(0xffffffffu, total, m);

    __shared__ float ws[PAIRS_PER_BLOCK];
    if (lane == 0) ws[wib] = total;
    __syncthreads();
    if (threadIdx.x == 0) {
        float s = 0.0f;
#pragma unroll
        for (int w = 0; w < PAIRS_PER_BLOCK; w++) s += ws[w];
        g_block_sums[blockIdx.x] = s;
    }
}

// ---------------------------------------------------------------------------
// Kernel 3: deterministic finalize — sum block partials in double, scale.
// ---------------------------------------------------------------------------
__global__ void __launch_bounds__(1024) finalize_kernel(float* out, int nblocks, int P) {
    double s = 0.0;
    for (int i = threadIdx.x; i < nblocks; i += 1024) s += (double)g_block_sums[i];
#pragma unroll
    for (int m = 16; m; m >>= 1) s += __shfl_xor_sync(0xffffffffu, s, m);
    __shared__ double sm[32];
    int lane = threadIdx.x & 31;
    int w = threadIdx.x >> 5;
    if (lane == 0) sm[w] = s;
    __syncthreads();
    if (w == 0) {
        double v = sm[lane];
#pragma unroll
        for (int m = 16; m; m >>= 1) v += __shfl_xor_sync(0xffffffffu, v, m);
        if (lane == 0) out[0] = (float)(v / ((double)P * 64.0));
    }
}

// ---------------------------------------------------------------------------
extern "C" void kernel_launch(void* const* d_in, const int* in_sizes, int n_in,
                              void* d_out, int out_size) {
    const float* z     = (const float*)d_in[0];
    const float* alpha = (const float*)d_in[1];
    const float* beta  = (const float*)d_in[2];
    const int* ap = (const int*)d_in[3];
    const int* pp = (const int*)d_in[4];
    const int* an = (const int*)d_in[5];
    const int* nn = (const int*)d_in[6];

    int P = in_sizes[3];
    int rows = in_sizes[0] / DD;  // B * S
    if (rows > MAX_ROWS) rows = MAX_ROWS;
    int nblocks = (P + PAIRS_PER_BLOCK - 1) / PAIRS_PER_BLOCK;
    if (nblocks > MAX_BLOCKS) nblocks = MAX_BLOCKS;

    norm_kernel<<<(rows + 7) / 8, 256>>>(z, rows);
    hib_kernel<<<nblocks, 256>>>(z, alpha, beta, ap, pp, an, nn, P);
    finalize_kernel<<<1, 1024>>>((float*)d_out, nblocks, P);
}